// round 12
// baseline (speedup 1.0000x reference)
#include <cuda_runtime.h>
#include <cuda_fp16.h>
#include <cstdint>

#define BMAX 16384
__device__ float g_xp[BMAX * 512];
__device__ float g_hs[BMAX * 128];
__device__ float g_c2wt[32 * 9 * 64];   // conv2 weights [ic][k][oc]
__device__ float g_d1wt[64 * 9 * 32];   // deconv1 conv-equiv weights [ic][k][oc]

__device__ __forceinline__ float fsig(float x) { return 1.0f / (1.0f + __expf(-x)); }
__device__ __forceinline__ float ftanh(float x) { return 2.0f * fsig(2.0f * x) - 1.0f; }
__device__ __forceinline__ void fma2(unsigned long long& acc, unsigned long long a, unsigned long long b) {
    asm("fma.rn.f32x2 %0, %1, %2, %0;" : "+l"(acc) : "l"(a), "l"(b));
}
__device__ __forceinline__ unsigned long long pk2(float x) {
    unsigned long long r; asm("mov.b64 %0, {%1,%2};" : "=l"(r) : "f"(x), "f"(x)); return r;
}
__device__ __forceinline__ float2 upk2(unsigned long long v) {
    float2 r; asm("mov.b64 {%0,%1}, %2;" : "=f"(r.x), "=f"(r.y) : "l"(v)); return r;
}
__device__ __forceinline__ __half2 u2h2(unsigned u) {
    __half2 h; *reinterpret_cast<unsigned*>(&h) = u; return h;
}
__device__ __forceinline__ uint32_t smem_u32(const void* p) {
    uint32_t a;
    asm("{ .reg .u64 t; cvta.to.shared.u64 t, %1; cvt.u32.u64 %0, t; }" : "=r"(a) : "l"(p));
    return a;
}
__device__ __forceinline__ void mbar_wait_cluster(uint32_t mb, uint32_t parity) {
    asm volatile(
        "{\n\t.reg .pred P1;\n\t"
        "WL_%=:\n\t"
        "mbarrier.try_wait.parity.acquire.cluster.shared::cta.b64 P1, [%0], %1, 0x989680;\n\t"
        "@P1 bra.uni WD_%=;\n\t"
        "bra.uni WL_%=;\n\t"
        "WD_%=:\n\t}"
        :: "r"(mb), "r"(parity) : "memory");
}

// ================= weight prep =================
__global__ void prep_kernel(const float* __restrict__ c2w, const float* __restrict__ d1w) {
    int i = blockIdx.x * 256 + threadIdx.x;
    if (i < 18432) {
        int oc = i / 288, r = i % 288, ic = r / 9, k = r % 9;
        g_c2wt[(ic * 9 + k) * 64 + oc] = c2w[i];
        int ic2 = i / 288, r2 = i % 288, oc2 = r2 / 9, kk = r2 % 9;
        g_d1wt[(ic2 * 9 + (8 - kk)) * 32 + oc2] = d1w[i];
    }
}

// ================= encoder + input projection (unchanged) =================
__global__ void __launch_bounds__(128) enc_kernel(
    const float* __restrict__ img, const float* __restrict__ act,
    const float* __restrict__ c1w, const float* __restrict__ c1b,
    const float* __restrict__ c2b,
    const float* __restrict__ encw, const float* __restrict__ encb,
    const float* __restrict__ wih, const float* __restrict__ bih,
    const float* __restrict__ bhh, int B)
{
    __shared__ float s_img[4][76];
    __shared__ float s_x[4][136];
    __shared__ float s_h2[4][1600];
    __shared__ float s_wt[4608];

    int tid = threadIdx.x, lane = tid & 31, w = tid >> 5;
    int gi = blockIdx.x * 4 + w;
    bool valid = gi < B;
    float* s_h1 = s_wt + w * 800;

    if (valid) {
        for (int i = lane; i < 75; i += 32) s_img[w][i] = img[gi * 75 + i];
        if (lane < 8) s_x[w][128 + lane] = act[gi * 8 + lane];
    }
    __syncwarp();

    int pidx[9];
    {
        int y = (lane < 25) ? lane / 5 : 0, x = (lane < 25) ? lane % 5 : 0;
        #pragma unroll
        for (int ky = 0; ky < 3; ky++)
            #pragma unroll
            for (int kx = 0; kx < 3; kx++) {
                int yy = y + ky - 1, xx = x + kx - 1;
                pidx[ky*3+kx] = (yy >= 0 && yy < 5 && xx >= 0 && xx < 5) ? yy*5+xx : -1;
            }
    }

    if (lane < 25) {
        float p1[27];
        #pragma unroll
        for (int ic = 0; ic < 3; ic++)
            #pragma unroll
            for (int j = 0; j < 9; j++)
                p1[ic*9+j] = (pidx[j] >= 0) ? s_img[w][ic*25 + pidx[j]] : 0.f;
        #pragma unroll 4
        for (int oc = 0; oc < 32; oc++) {
            float a = __ldg(&c1b[oc]);
            #pragma unroll
            for (int k = 0; k < 27; k++) a += p1[k] * __ldg(&c1w[oc*27+k]);
            s_h1[oc*25+lane] = fmaxf(a, 0.f);
        }
    }
    __syncwarp();

    if (lane < 25) {
        unsigned long long acc2[32];
        #pragma unroll
        for (int q = 0; q < 32; q++) acc2[q] = 0ull;
        for (int ic = 0; ic < 32; ic++) {
            const float* hp = s_h1 + ic * 25;
            unsigned long long p2[9];
            #pragma unroll
            for (int j = 0; j < 9; j++)
                p2[j] = pk2((pidx[j] >= 0) ? hp[pidx[j]] : 0.f);
            const ulonglong2* wt = reinterpret_cast<const ulonglong2*>(&g_c2wt[ic * 576]);
            #pragma unroll
            for (int k = 0; k < 9; k++) {
                #pragma unroll
                for (int q = 0; q < 16; q++) {
                    ulonglong2 wv = __ldg(&wt[k*16 + q]);
                    fma2(acc2[q*2],   p2[k], wv.x);
                    fma2(acc2[q*2+1], p2[k], wv.y);
                }
            }
        }
        #pragma unroll
        for (int q = 0; q < 32; q++) {
            float2 v = upk2(acc2[q]);
            s_h2[w][(2*q)*25   + lane] = fmaxf(v.x + __ldg(&c2b[2*q]),   0.f);
            s_h2[w][(2*q+1)*25 + lane] = fmaxf(v.y + __ldg(&c2b[2*q+1]), 0.f);
        }
    }
    __syncthreads();

    for (int ot = 0; ot < 4; ot++) {
        float acc = 0.f;
        for (int kt = 0; kt < 13; kt++) {
            int k0 = kt * 128, klen = (kt == 12) ? 64 : 128;
            __syncthreads();
            for (int idx = tid; idx < 32 * klen; idx += 128) {
                int r = idx / klen, k = idx - r * klen;
                s_wt[r*132 + k] = encw[(ot*32 + r)*1600 + k0 + k];
            }
            __syncthreads();
            const float4* wt4 = reinterpret_cast<const float4*>(&s_wt[lane*132]);
            const float4* h4  = reinterpret_cast<const float4*>(&s_h2[w][k0]);
            int n4 = klen >> 2;
            #pragma unroll 8
            for (int q = 0; q < n4; q++) {
                float4 wv = wt4[q], hv = h4[q];
                acc += wv.x*hv.x + wv.y*hv.y + wv.z*hv.z + wv.w*hv.w;
            }
        }
        s_x[w][ot*32 + lane] = acc + __ldg(&encb[ot*32 + lane]);
    }

    for (int ot = 0; ot < 16; ot++) {
        __syncthreads();
        for (int idx = tid; idx < 32 * 136; idx += 128) {
            int r = idx / 136, k = idx - r * 136;
            s_wt[r*144 + k] = wih[(ot*32 + r)*136 + k];
        }
        __syncthreads();
        float acc = 0.f;
        const float4* wt4 = reinterpret_cast<const float4*>(&s_wt[lane*144]);
        const float4* xv4 = reinterpret_cast<const float4*>(&s_x[w][0]);
        #pragma unroll 17
        for (int q = 0; q < 34; q++) {
            float4 wv = wt4[q], xv = xv4[q];
            acc += wv.x*xv.x + wv.y*xv.y + wv.z*xv.z + wv.w*xv.w;
        }
        if (valid) {
            int o = ot*32 + lane;
            g_xp[gi*512 + o] = acc + __ldg(&bih[o]) + __ldg(&bhh[o]);
        }
    }
}

// ================= LSTM: 4-CTA cluster, one gate per CTA =================
// CTA rank computes gate `rank` for all 128 rows (thread = row, full K).
// HFMA2 issue floor: 64 inst/warp, 1 warp/SMSP -> 128 cyc/SMSP (was 512).
// Activations exchanged via DSMEM (st.shared::cluster) + mbarrier
// (512 arrivals/phase: 3x128 remote + 128 local). Epilogue replicated in
// every CTA (c identical); h double-buffered locally; ONE local bar/step.
__global__ void __launch_bounds__(128) __cluster_dims__(4, 1, 1) lstm_kernel(
    const float* __restrict__ whh, float* __restrict__ d_out, int B, int out_size)
{
    __shared__ __align__(16) __half s_h[2][128];
    __shared__ __align__(16) float s_act[2][512];
    __shared__ __align__(8) unsigned long long s_mbar;

    int tid = threadIdx.x;
    unsigned rank;
    asm("mov.u32 %0, %%cluster_ctarank;" : "=r"(rank));

    // weights for global gate-row rank*128 + tid
    __half2 w2[64];
    {
        const float4* rw = reinterpret_cast<const float4*>(&whh[(rank * 128 + tid) * 128]);
        #pragma unroll
        for (int j = 0; j < 32; j++) {
            float4 v = __ldg(&rw[j]);
            w2[2*j]   = __floats2half2_rn(v.x, v.y);
            w2[2*j+1] = __floats2half2_rn(v.z, v.w);
        }
    }
    uint32_t barAddr = smem_u32(&s_mbar);
    if (tid == 0)
        asm volatile("mbarrier.init.shared.b64 [%0], %1;" :: "r"(barAddr), "r"(512) : "memory");
    s_h[0][tid] = __float2half_rn(0.f);
    __syncthreads();
    // cluster-wide: mbarriers initialized before any remote arrive
    asm volatile("barrier.cluster.arrive.aligned;" ::: "memory");
    asm volatile("barrier.cluster.wait.aligned;" ::: "memory");

    // precompute peer addresses (act buffer base + mbar) once
    uint32_t actBase = smem_u32(&s_act[0][0]);
    uint32_t rAct[3], rBar[3];
    #pragma unroll
    for (int p = 0; p < 3; p++) {
        unsigned peer = (rank + 1 + p) & 3;
        asm("mapa.shared::cluster.u32 %0, %1, %2;" : "=r"(rAct[p]) : "r"(actBase), "r"(peer));
        asm("mapa.shared::cluster.u32 %0, %1, %2;" : "=r"(rBar[p]) : "r"(barAddr), "r"(peer));
    }

    int xsel = rank * 128 + tid;
    float xp0 = __ldg(&g_xp[xsel]);
    float xp1 = (B > 1) ? __ldg(&g_xp[512 + xsel]) : 0.f;

    float c = 0.f;
    for (int t = 0; t < B; t++) {
        // ---- matvec: full 128-dot for row tid, gate rank ----
        const uint4* sh4 = reinterpret_cast<const uint4*>(s_h[t & 1]);
        __half2 hacc[4];
        #pragma unroll
        for (int ch = 0; ch < 4; ch++) {
            unsigned hw[16];
            uint4 q0 = sh4[ch*4+0], q1 = sh4[ch*4+1], q2 = sh4[ch*4+2], q3 = sh4[ch*4+3];
            hw[0]=q0.x; hw[1]=q0.y; hw[2]=q0.z; hw[3]=q0.w;
            hw[4]=q1.x; hw[5]=q1.y; hw[6]=q1.z; hw[7]=q1.w;
            hw[8]=q2.x; hw[9]=q2.y; hw[10]=q2.z; hw[11]=q2.w;
            hw[12]=q3.x; hw[13]=q3.y; hw[14]=q3.z; hw[15]=q3.w;
            __half2 acc = __float2half2_rn(0.f);
            #pragma unroll
            for (int j = 0; j < 16; j++)
                acc = __hfma2(w2[ch*16 + j], u2h2(hw[j]), acc);
            hacc[ch] = acc;
        }
        __half2 s01 = __hadd2(hacc[0], hacc[1]);
        __half2 s23 = __hadd2(hacc[2], hacc[3]);
        float2 fs = __half22float2(__hadd2(s01, s23));
        float pre = xp0 + fs.x + fs.y;

        xp0 = xp1;
        if (t + 2 < B) xp1 = __ldg(&g_xp[(t+2)*512 + xsel]);

        float a = (rank == 2) ? ftanh(pre) : fsig(pre);   // gate 2 = g

        // ---- publish activation: local + 3 peers, then arrives ----
        unsigned boff = (((t & 1) * 512) + rank * 128 + tid) * 4;
        s_act[t & 1][rank * 128 + tid] = a;
        #pragma unroll
        for (int p = 0; p < 3; p++)
            asm volatile("st.shared::cluster.f32 [%0], %1;" :: "r"(rAct[p] + boff), "f"(a) : "memory");
        #pragma unroll
        for (int p = 0; p < 3; p++)
            asm volatile("mbarrier.arrive.release.cluster.shared::cluster.b64 _, [%0];"
                         :: "r"(rBar[p]) : "memory");
        asm volatile("mbarrier.arrive.release.cluster.shared::cta.b64 _, [%0];"
                     :: "r"(barAddr) : "memory");

        mbar_wait_cluster(barAddr, (uint32_t)(t & 1));

        // ---- replicated epilogue (c identical in all CTAs) ----
        const float* ab = s_act[t & 1];
        float gi = ab[tid];
        float gf = ab[128 + tid];
        float gg = ab[256 + tid];
        float go = ab[384 + tid];
        c = fmaf(gf, c, gi * gg);
        float h = go * ftanh(c);
        s_h[(t + 1) & 1][tid] = __float2half_rn(h);
        if (rank == 0) {
            g_hs[t*128 + tid] = h;
            if (t == B - 1) {
                d_out[out_size - 256 + tid] = h;
                d_out[out_size - 128 + tid] = c;
            }
        }
        __syncthreads();   // h buffer ready for next matvec
    }

    // no CTA may exit while peers still target its SMEM
    asm volatile("barrier.cluster.arrive.aligned;" ::: "memory");
    asm volatile("barrier.cluster.wait.aligned;" ::: "memory");
}

// ================= decoder (unchanged) =================
__global__ void __launch_bounds__(128) dec_kernel(
    const float* __restrict__ decw, const float* __restrict__ decb,
    const float* __restrict__ d1b,
    const float* __restrict__ d2w, const float* __restrict__ d2b,
    float* __restrict__ out, int B)
{
    __shared__ float s_hs[4][128];
    __shared__ float s_d[4][1600];
    __shared__ float s_wt[4224];
    __shared__ float s_w2f[864];

    int tid = threadIdx.x, lane = tid & 31, w = tid >> 5;
    int gi = blockIdx.x * 4 + w;
    bool valid = gi < B;

    for (int i = tid; i < 864; i += 128) {
        int ic = i / 27, rem = i % 27, oc = rem / 9, k = rem % 9;
        s_w2f[i] = d2w[(ic*3 + oc)*9 + (8 - k)];
    }
    if (valid)
        for (int i = lane; i < 128; i += 32) s_hs[w][i] = g_hs[gi*128 + i];

    for (int ot = 0; ot < 50; ot++) {
        __syncthreads();
        for (int idx = tid; idx < 4096; idx += 128) {
            int r = idx >> 7, k = idx & 127;
            s_wt[r*132 + k] = decw[(ot*32 + r)*128 + k];
        }
        __syncthreads();
        float acc = 0.f;
        const float4* wt4 = reinterpret_cast<const float4*>(&s_wt[lane*132]);
        const float4* h4  = reinterpret_cast<const float4*>(&s_hs[w][0]);
        #pragma unroll 8
        for (int q = 0; q < 32; q++) {
            float4 wv = wt4[q], hv = h4[q];
            acc += wv.x*hv.x + wv.y*hv.y + wv.z*hv.z + wv.w*hv.w;
        }
        s_d[w][ot*32 + lane] = acc + __ldg(&decb[ot*32 + lane]);
    }
    __syncthreads();

    float* s_h1 = s_wt + w * 800;
    int pidx[9];
    {
        int y = (lane < 25) ? lane / 5 : 0, x = (lane < 25) ? lane % 5 : 0;
        #pragma unroll
        for (int ky = 0; ky < 3; ky++)
            #pragma unroll
            for (int kx = 0; kx < 3; kx++) {
                int yy = y + ky - 1, xx = x + kx - 1;
                pidx[ky*3+kx] = (yy >= 0 && yy < 5 && xx >= 0 && xx < 5) ? yy*5+xx : -1;
            }
    }

    if (lane < 25) {
        unsigned long long acc2[16];
        #pragma unroll
        for (int q = 0; q < 16; q++) acc2[q] = 0ull;
        for (int ic = 0; ic < 64; ic++) {
            const float* dp = &s_d[w][ic * 25];
            unsigned long long p2[9];
            #pragma unroll
            for (int j = 0; j < 9; j++)
                p2[j] = pk2((pidx[j] >= 0) ? dp[pidx[j]] : 0.f);
            const ulonglong2* wt = reinterpret_cast<const ulonglong2*>(&g_d1wt[ic * 288]);
            #pragma unroll
            for (int k = 0; k < 9; k++) {
                #pragma unroll
                for (int q = 0; q < 8; q++) {
                    ulonglong2 wv = __ldg(&wt[k*8 + q]);
                    fma2(acc2[q*2],   p2[k], wv.x);
                    fma2(acc2[q*2+1], p2[k], wv.y);
                }
            }
        }
        #pragma unroll
        for (int q = 0; q < 16; q++) {
            float2 v = upk2(acc2[q]);
            s_h1[(2*q)*25   + lane] = fmaxf(v.x + __ldg(&d1b[2*q]),   0.f);
            s_h1[(2*q+1)*25 + lane] = fmaxf(v.y + __ldg(&d1b[2*q+1]), 0.f);
        }
    }
    __syncwarp();

    if (valid && lane < 25) {
        float acc[3] = {__ldg(&d2b[0]), __ldg(&d2b[1]), __ldg(&d2b[2])};
        for (int ic = 0; ic < 32; ic++) {
            float p[9];
            #pragma unroll
            for (int j = 0; j < 9; j++)
                p[j] = (pidx[j] >= 0) ? s_h1[ic*25 + pidx[j]] : 0.f;
            #pragma unroll
            for (int oc = 0; oc < 3; oc++) {
                float a = acc[oc];
                #pragma unroll
                for (int k = 0; k < 9; k++) a += p[k] * s_w2f[ic*27 + oc*9 + k];
                acc[oc] = a;
            }
        }
        #pragma unroll
        for (int oc = 0; oc < 3; oc++)
            out[gi*75 + oc*25 + lane] = fsig(acc[oc]);
    }
}

extern "C" void kernel_launch(void* const* d_in, const int* in_sizes, int n_in,
                              void* d_out, int out_size)
{
    const float* img   = (const float*)d_in[0];
    const float* act   = (const float*)d_in[1];
    const float* c1w   = (const float*)d_in[2];
    const float* c1b   = (const float*)d_in[3];
    const float* c2w   = (const float*)d_in[4];
    const float* c2b   = (const float*)d_in[5];
    const float* encw  = (const float*)d_in[6];
    const float* encb  = (const float*)d_in[7];
    const float* wih   = (const float*)d_in[8];
    const float* whh   = (const float*)d_in[9];
    const float* bih   = (const float*)d_in[10];
    const float* bhh   = (const float*)d_in[11];
    const float* decw  = (const float*)d_in[12];
    const float* decb  = (const float*)d_in[13];
    const float* d1w   = (const float*)d_in[14];
    const float* d1b   = (const float*)d_in[15];
    const float* d2w   = (const float*)d_in[16];
    const float* d2b   = (const float*)d_in[17];
    float* out = (float*)d_out;

    int B = in_sizes[0] / 75;
    int blocks = (B + 3) / 4;

    prep_kernel<<<72, 256>>>(c2w, d1w);
    enc_kernel<<<blocks, 128>>>(img, act, c1w, c1b, c2b, encw, encb, wih, bih, bhh, B);
    lstm_kernel<<<4, 128>>>(whh, out, B, out_size);   // 4-CTA cluster, one gate per CTA
    dec_kernel<<<blocks, 128>>>(decw, decb, d1b, d2w, d2b, out, B);
}

// round 13
// speedup vs baseline: 1.2840x; 1.2840x over previous
#include <cuda_runtime.h>
#include <cuda_fp16.h>
#include <cstdint>

#define BMAX 16384
__device__ float g_xp[BMAX * 512];
__device__ float g_hs[BMAX * 128];
__device__ float g_c2wt[32 * 9 * 64];   // conv2 weights [ic][k][oc]
__device__ float g_d1wt[64 * 9 * 32];   // deconv1 conv-equiv weights [ic][k][oc]

__device__ __forceinline__ float fsig(float x) { return 1.0f / (1.0f + __expf(-x)); }
__device__ __forceinline__ float ftanh(float x) { return 2.0f * fsig(2.0f * x) - 1.0f; }
__device__ __forceinline__ void fma2(unsigned long long& acc, unsigned long long a, unsigned long long b) {
    asm("fma.rn.f32x2 %0, %1, %2, %0;" : "+l"(acc) : "l"(a), "l"(b));
}
__device__ __forceinline__ unsigned long long pk2(float x) {
    unsigned long long r; asm("mov.b64 %0, {%1,%2};" : "=l"(r) : "f"(x), "f"(x)); return r;
}
__device__ __forceinline__ float2 upk2(unsigned long long v) {
    float2 r; asm("mov.b64 {%0,%1}, %2;" : "=f"(r.x), "=f"(r.y) : "l"(v)); return r;
}
__device__ __forceinline__ __half2 u2h2(unsigned u) {
    __half2 h; *reinterpret_cast<unsigned*>(&h) = u; return h;
}
__device__ __forceinline__ uint32_t smem_u32(const void* p) {
    uint32_t a;
    asm("{ .reg .u64 t; cvta.to.shared.u64 t, %1; cvt.u32.u64 %0, t; }" : "=r"(a) : "l"(p));
    return a;
}
__device__ __forceinline__ void mbar_wait_cluster(uint32_t mb, uint32_t parity) {
    asm volatile(
        "{\n\t.reg .pred P1;\n\t"
        "WL_%=:\n\t"
        "mbarrier.try_wait.parity.acquire.cluster.shared::cta.b64 P1, [%0], %1, 0x989680;\n\t"
        "@P1 bra.uni WD_%=;\n\t"
        "bra.uni WL_%=;\n\t"
        "WD_%=:\n\t}"
        :: "r"(mb), "r"(parity) : "memory");
}

// ================= weight prep =================
__global__ void prep_kernel(const float* __restrict__ c2w, const float* __restrict__ d1w) {
    int i = blockIdx.x * 256 + threadIdx.x;
    if (i < 18432) {
        int oc = i / 288, r = i % 288, ic = r / 9, k = r % 9;
        g_c2wt[(ic * 9 + k) * 64 + oc] = c2w[i];
        int ic2 = i / 288, r2 = i % 288, oc2 = r2 / 9, kk = r2 % 9;
        g_d1wt[(ic2 * 9 + (8 - kk)) * 32 + oc2] = d1w[i];
    }
}

// ================= encoder + input projection (unchanged) =================
__global__ void __launch_bounds__(128) enc_kernel(
    const float* __restrict__ img, const float* __restrict__ act,
    const float* __restrict__ c1w, const float* __restrict__ c1b,
    const float* __restrict__ c2b,
    const float* __restrict__ encw, const float* __restrict__ encb,
    const float* __restrict__ wih, const float* __restrict__ bih,
    const float* __restrict__ bhh, int B)
{
    __shared__ float s_img[4][76];
    __shared__ float s_x[4][136];
    __shared__ float s_h2[4][1600];
    __shared__ float s_wt[4608];

    int tid = threadIdx.x, lane = tid & 31, w = tid >> 5;
    int gi = blockIdx.x * 4 + w;
    bool valid = gi < B;
    float* s_h1 = s_wt + w * 800;

    if (valid) {
        for (int i = lane; i < 75; i += 32) s_img[w][i] = img[gi * 75 + i];
        if (lane < 8) s_x[w][128 + lane] = act[gi * 8 + lane];
    }
    __syncwarp();

    int pidx[9];
    {
        int y = (lane < 25) ? lane / 5 : 0, x = (lane < 25) ? lane % 5 : 0;
        #pragma unroll
        for (int ky = 0; ky < 3; ky++)
            #pragma unroll
            for (int kx = 0; kx < 3; kx++) {
                int yy = y + ky - 1, xx = x + kx - 1;
                pidx[ky*3+kx] = (yy >= 0 && yy < 5 && xx >= 0 && xx < 5) ? yy*5+xx : -1;
            }
    }

    if (lane < 25) {
        float p1[27];
        #pragma unroll
        for (int ic = 0; ic < 3; ic++)
            #pragma unroll
            for (int j = 0; j < 9; j++)
                p1[ic*9+j] = (pidx[j] >= 0) ? s_img[w][ic*25 + pidx[j]] : 0.f;
        #pragma unroll 4
        for (int oc = 0; oc < 32; oc++) {
            float a = __ldg(&c1b[oc]);
            #pragma unroll
            for (int k = 0; k < 27; k++) a += p1[k] * __ldg(&c1w[oc*27+k]);
            s_h1[oc*25+lane] = fmaxf(a, 0.f);
        }
    }
    __syncwarp();

    if (lane < 25) {
        unsigned long long acc2[32];
        #pragma unroll
        for (int q = 0; q < 32; q++) acc2[q] = 0ull;
        for (int ic = 0; ic < 32; ic++) {
            const float* hp = s_h1 + ic * 25;
            unsigned long long p2[9];
            #pragma unroll
            for (int j = 0; j < 9; j++)
                p2[j] = pk2((pidx[j] >= 0) ? hp[pidx[j]] : 0.f);
            const ulonglong2* wt = reinterpret_cast<const ulonglong2*>(&g_c2wt[ic * 576]);
            #pragma unroll
            for (int k = 0; k < 9; k++) {
                #pragma unroll
                for (int q = 0; q < 16; q++) {
                    ulonglong2 wv = __ldg(&wt[k*16 + q]);
                    fma2(acc2[q*2],   p2[k], wv.x);
                    fma2(acc2[q*2+1], p2[k], wv.y);
                }
            }
        }
        #pragma unroll
        for (int q = 0; q < 32; q++) {
            float2 v = upk2(acc2[q]);
            s_h2[w][(2*q)*25   + lane] = fmaxf(v.x + __ldg(&c2b[2*q]),   0.f);
            s_h2[w][(2*q+1)*25 + lane] = fmaxf(v.y + __ldg(&c2b[2*q+1]), 0.f);
        }
    }
    __syncthreads();

    for (int ot = 0; ot < 4; ot++) {
        float acc = 0.f;
        for (int kt = 0; kt < 13; kt++) {
            int k0 = kt * 128, klen = (kt == 12) ? 64 : 128;
            __syncthreads();
            for (int idx = tid; idx < 32 * klen; idx += 128) {
                int r = idx / klen, k = idx - r * klen;
                s_wt[r*132 + k] = encw[(ot*32 + r)*1600 + k0 + k];
            }
            __syncthreads();
            const float4* wt4 = reinterpret_cast<const float4*>(&s_wt[lane*132]);
            const float4* h4  = reinterpret_cast<const float4*>(&s_h2[w][k0]);
            int n4 = klen >> 2;
            #pragma unroll 8
            for (int q = 0; q < n4; q++) {
                float4 wv = wt4[q], hv = h4[q];
                acc += wv.x*hv.x + wv.y*hv.y + wv.z*hv.z + wv.w*hv.w;
            }
        }
        s_x[w][ot*32 + lane] = acc + __ldg(&encb[ot*32 + lane]);
    }

    for (int ot = 0; ot < 16; ot++) {
        __syncthreads();
        for (int idx = tid; idx < 32 * 136; idx += 128) {
            int r = idx / 136, k = idx - r * 136;
            s_wt[r*144 + k] = wih[(ot*32 + r)*136 + k];
        }
        __syncthreads();
        float acc = 0.f;
        const float4* wt4 = reinterpret_cast<const float4*>(&s_wt[lane*144]);
        const float4* xv4 = reinterpret_cast<const float4*>(&s_x[w][0]);
        #pragma unroll 17
        for (int q = 0; q < 34; q++) {
            float4 wv = wt4[q], xv = xv4[q];
            acc += wv.x*xv.x + wv.y*xv.y + wv.z*xv.z + wv.w*xv.w;
        }
        if (valid) {
            int o = ot*32 + lane;
            g_xp[gi*512 + o] = acc + __ldg(&bih[o]) + __ldg(&bhh[o]);
        }
    }
}

// ================= LSTM: 2-CTA cluster, split by ROW =================
// CTA rank owns h rows [rank*64, rank*64+64): all 4 gates for those rows
// (thread = (gate, row)). Gate combine is CTA-LOCAL (s_act + syncthreads).
// Cross-CTA traffic per step = 64 f16 h values (st.shared::cluster.u16),
// signaled by 64 remote arrives on a count-64 mbarrier (vs R12's 512).
// HFMA2 issue floor: 2 warps/SMSP x 64 x rt2 = 256 cyc (half of R11).
__global__ void __launch_bounds__(256) __cluster_dims__(2, 1, 1) lstm_kernel(
    const float* __restrict__ whh, float* __restrict__ d_out, int B, int out_size)
{
    __shared__ __align__(16) __half s_h[2][128];
    __shared__ float s_act[256];
    __shared__ __align__(8) unsigned long long s_mbar;

    int tid = threadIdx.x;
    unsigned rank;
    asm("mov.u32 %0, %%cluster_ctarank;" : "=r"(rank));
    int gate = tid >> 6;          // 0:i 1:f 2:g 3:o (uniform per 2 warps)
    int lrow = tid & 63;
    int grow = rank * 64 + lrow;  // global h row (for epilogue threads)

    // weights for gate-row: gate*128 + grow
    __half2 w2[64];
    {
        const float4* rw = reinterpret_cast<const float4*>(&whh[(gate * 128 + grow) * 128]);
        #pragma unroll
        for (int j = 0; j < 32; j++) {
            float4 v = __ldg(&rw[j]);
            w2[2*j]   = __floats2half2_rn(v.x, v.y);
            w2[2*j+1] = __floats2half2_rn(v.z, v.w);
        }
    }
    uint32_t barAddr = smem_u32(&s_mbar);
    if (tid == 0)
        asm volatile("mbarrier.init.shared.b64 [%0], %1;" :: "r"(barAddr), "r"(64) : "memory");
    if (tid < 128) s_h[0][tid] = __float2half_rn(0.f);
    __syncthreads();
    asm volatile("barrier.cluster.arrive.aligned;" ::: "memory");
    asm volatile("barrier.cluster.wait.aligned;" ::: "memory");

    // peer addresses (other CTA's s_h base + mbar)
    unsigned peer = rank ^ 1u;
    uint32_t rH, rBar;
    {
        uint32_t hBase = smem_u32(&s_h[0][0]);
        asm("mapa.shared::cluster.u32 %0, %1, %2;" : "=r"(rH) : "r"(hBase), "r"(peer));
        asm("mapa.shared::cluster.u32 %0, %1, %2;" : "=r"(rBar) : "r"(barAddr), "r"(peer));
    }

    int xsel = gate * 128 + grow;
    float xp0 = __ldg(&g_xp[xsel]);
    float xp1 = (B > 1) ? __ldg(&g_xp[512 + xsel]) : 0.f;

    float c = 0.f;   // live in tid<64 (row lrow of this CTA's half)
    for (int t = 0; t < B; t++) {
        // ---- matvec: full 128-dot (h complete in local smem) ----
        const uint4* sh4 = reinterpret_cast<const uint4*>(s_h[t & 1]);
        __half2 hacc[4];
        #pragma unroll
        for (int ch = 0; ch < 4; ch++) {
            unsigned hw[16];
            uint4 q0 = sh4[ch*4+0], q1 = sh4[ch*4+1], q2 = sh4[ch*4+2], q3 = sh4[ch*4+3];
            hw[0]=q0.x; hw[1]=q0.y; hw[2]=q0.z; hw[3]=q0.w;
            hw[4]=q1.x; hw[5]=q1.y; hw[6]=q1.z; hw[7]=q1.w;
            hw[8]=q2.x; hw[9]=q2.y; hw[10]=q2.z; hw[11]=q2.w;
            hw[12]=q3.x; hw[13]=q3.y; hw[14]=q3.z; hw[15]=q3.w;
            __half2 acc = __float2half2_rn(0.f);
            #pragma unroll
            for (int j = 0; j < 16; j++)
                acc = __hfma2(w2[ch*16 + j], u2h2(hw[j]), acc);
            hacc[ch] = acc;
        }
        __half2 s01 = __hadd2(hacc[0], hacc[1]);
        __half2 s23 = __hadd2(hacc[2], hacc[3]);
        float2 fs = __half22float2(__hadd2(s01, s23));
        float pre = xp0 + fs.x + fs.y;

        xp0 = xp1;
        if (t + 2 < B) xp1 = __ldg(&g_xp[(t+2)*512 + xsel]);

        float a = (gate == 2) ? ftanh(pre) : fsig(pre);
        s_act[tid] = a;
        __syncthreads();                              // local acts ready

        // ---- epilogue: tid<64 own row grow ----
        if (tid < 64) {
            float gi = s_act[lrow];
            float gf = s_act[64 + lrow];
            float gg = s_act[128 + lrow];
            float go = s_act[192 + lrow];
            c = fmaf(gf, c, gi * gg);
            float h = go * ftanh(c);
            __half hh = __float2half_rn(h);
            s_h[(t + 1) & 1][grow] = hh;              // local half
            // publish to peer: 2B store + release-arrive
            unsigned short hb = __half_as_ushort(hh);
            unsigned off = (unsigned)((((t + 1) & 1) * 128 + grow) * 2);
            asm volatile("st.shared::cluster.u16 [%0], %1;" :: "r"(rH + off), "h"(hb) : "memory");
            asm volatile("mbarrier.arrive.release.cluster.shared::cluster.b64 _, [%0];"
                         :: "r"(rBar) : "memory");
            g_hs[t*128 + grow] = h;
            if (t == B - 1) {
                d_out[out_size - 256 + grow] = h;
                d_out[out_size - 128 + grow] = c;
            }
        }
        __syncthreads();                              // local h half ready
        mbar_wait_cluster(barAddr, (uint32_t)(t & 1));   // remote half delivered
    }

    asm volatile("barrier.cluster.arrive.aligned;" ::: "memory");
    asm volatile("barrier.cluster.wait.aligned;" ::: "memory");
}

// ================= decoder (unchanged) =================
__global__ void __launch_bounds__(128) dec_kernel(
    const float* __restrict__ decw, const float* __restrict__ decb,
    const float* __restrict__ d1b,
    const float* __restrict__ d2w, const float* __restrict__ d2b,
    float* __restrict__ out, int B)
{
    __shared__ float s_hs[4][128];
    __shared__ float s_d[4][1600];
    __shared__ float s_wt[4224];
    __shared__ float s_w2f[864];

    int tid = threadIdx.x, lane = tid & 31, w = tid >> 5;
    int gi = blockIdx.x * 4 + w;
    bool valid = gi < B;

    for (int i = tid; i < 864; i += 128) {
        int ic = i / 27, rem = i % 27, oc = rem / 9, k = rem % 9;
        s_w2f[i] = d2w[(ic*3 + oc)*9 + (8 - k)];
    }
    if (valid)
        for (int i = lane; i < 128; i += 32) s_hs[w][i] = g_hs[gi*128 + i];

    for (int ot = 0; ot < 50; ot++) {
        __syncthreads();
        for (int idx = tid; idx < 4096; idx += 128) {
            int r = idx >> 7, k = idx & 127;
            s_wt[r*132 + k] = decw[(ot*32 + r)*128 + k];
        }
        __syncthreads();
        float acc = 0.f;
        const float4* wt4 = reinterpret_cast<const float4*>(&s_wt[lane*132]);
        const float4* h4  = reinterpret_cast<const float4*>(&s_hs[w][0]);
        #pragma unroll 8
        for (int q = 0; q < 32; q++) {
            float4 wv = wt4[q], hv = h4[q];
            acc += wv.x*hv.x + wv.y*hv.y + wv.z*hv.z + wv.w*hv.w;
        }
        s_d[w][ot*32 + lane] = acc + __ldg(&decb[ot*32 + lane]);
    }
    __syncthreads();

    float* s_h1 = s_wt + w * 800;
    int pidx[9];
    {
        int y = (lane < 25) ? lane / 5 : 0, x = (lane < 25) ? lane % 5 : 0;
        #pragma unroll
        for (int ky = 0; ky < 3; ky++)
            #pragma unroll
            for (int kx = 0; kx < 3; kx++) {
                int yy = y + ky - 1, xx = x + kx - 1;
                pidx[ky*3+kx] = (yy >= 0 && yy < 5 && xx >= 0 && xx < 5) ? yy*5+xx : -1;
            }
    }

    if (lane < 25) {
        unsigned long long acc2[16];
        #pragma unroll
        for (int q = 0; q < 16; q++) acc2[q] = 0ull;
        for (int ic = 0; ic < 64; ic++) {
            const float* dp = &s_d[w][ic * 25];
            unsigned long long p2[9];
            #pragma unroll
            for (int j = 0; j < 9; j++)
                p2[j] = pk2((pidx[j] >= 0) ? dp[pidx[j]] : 0.f);
            const ulonglong2* wt = reinterpret_cast<const ulonglong2*>(&g_d1wt[ic * 288]);
            #pragma unroll
            for (int k = 0; k < 9; k++) {
                #pragma unroll
                for (int q = 0; q < 8; q++) {
                    ulonglong2 wv = __ldg(&wt[k*8 + q]);
                    fma2(acc2[q*2],   p2[k], wv.x);
                    fma2(acc2[q*2+1], p2[k], wv.y);
                }
            }
        }
        #pragma unroll
        for (int q = 0; q < 16; q++) {
            float2 v = upk2(acc2[q]);
            s_h1[(2*q)*25   + lane] = fmaxf(v.x + __ldg(&d1b[2*q]),   0.f);
            s_h1[(2*q+1)*25 + lane] = fmaxf(v.y + __ldg(&d1b[2*q+1]), 0.f);
        }
    }
    __syncwarp();

    if (valid && lane < 25) {
        float acc[3] = {__ldg(&d2b[0]), __ldg(&d2b[1]), __ldg(&d2b[2])};
        for (int ic = 0; ic < 32; ic++) {
            float p[9];
            #pragma unroll
            for (int j = 0; j < 9; j++)
                p[j] = (pidx[j] >= 0) ? s_h1[ic*25 + pidx[j]] : 0.f;
            #pragma unroll
            for (int oc = 0; oc < 3; oc++) {
                float a = acc[oc];
                #pragma unroll
                for (int k = 0; k < 9; k++) a += p[k] * s_w2f[ic*27 + oc*9 + k];
                acc[oc] = a;
            }
        }
        #pragma unroll
        for (int oc = 0; oc < 3; oc++)
            out[gi*75 + oc*25 + lane] = fsig(acc[oc]);
    }
}

extern "C" void kernel_launch(void* const* d_in, const int* in_sizes, int n_in,
                              void* d_out, int out_size)
{
    const float* img   = (const float*)d_in[0];
    const float* act   = (const float*)d_in[1];
    const float* c1w   = (const float*)d_in[2];
    const float* c1b   = (const float*)d_in[3];
    const float* c2w   = (const float*)d_in[4];
    const float* c2b   = (const float*)d_in[5];
    const float* encw  = (const float*)d_in[6];
    const float* encb  = (const float*)d_in[7];
    const float* wih   = (const float*)d_in[8];
    const float* whh   = (const float*)d_in[9];
    const float* bih   = (const float*)d_in[10];
    const float* bhh   = (const float*)d_in[11];
    const float* decw  = (const float*)d_in[12];
    const float* decb  = (const float*)d_in[13];
    const float* d1w   = (const float*)d_in[14];
    const float* d1b   = (const float*)d_in[15];
    const float* d2w   = (const float*)d_in[16];
    const float* d2b   = (const float*)d_in[17];
    float* out = (float*)d_out;

    int B = in_sizes[0] / 75;
    int blocks = (B + 3) / 4;

    prep_kernel<<<72, 256>>>(c2w, d1w);
    enc_kernel<<<blocks, 128>>>(img, act, c1w, c1b, c2b, encw, encb, wih, bih, bhh, B);
    lstm_kernel<<<2, 256>>>(whh, out, B, out_size);   // 2-CTA cluster, row-split
    dec_kernel<<<blocks, 128>>>(decw, decb, d1b, d2w, d2b, out, B);
}

// round 14
// speedup vs baseline: 1.7571x; 1.3685x over previous
#include <cuda_runtime.h>
#include <cuda_fp16.h>
#include <cstdint>

#define BMAX 16384
__device__ float g_xp[BMAX * 512];
__device__ float g_hs[BMAX * 128];
__device__ float g_c2wt[32 * 9 * 64];   // conv2 weights [ic][k][oc]
__device__ float g_d1wt[64 * 9 * 32];   // deconv1 conv-equiv weights [ic][k][oc]

// fast activations: MUFU-only (no IEEE div). __fdividef = a * rcp.approx(b).
__device__ __forceinline__ float fsig(float x) { return __fdividef(1.0f, 1.0f + __expf(-x)); }
__device__ __forceinline__ float ftanh(float x) { return 2.0f * fsig(2.0f * x) - 1.0f; }
__device__ __forceinline__ void fma2(unsigned long long& acc, unsigned long long a, unsigned long long b) {
    asm("fma.rn.f32x2 %0, %1, %2, %0;" : "+l"(acc) : "l"(a), "l"(b));
}
__device__ __forceinline__ unsigned long long pk2(float x) {
    unsigned long long r; asm("mov.b64 %0, {%1,%2};" : "=l"(r) : "f"(x), "f"(x)); return r;
}
__device__ __forceinline__ float2 upk2(unsigned long long v) {
    float2 r; asm("mov.b64 {%0,%1}, %2;" : "=f"(r.x), "=f"(r.y) : "l"(v)); return r;
}
__device__ __forceinline__ __half2 u2h2(unsigned u) {
    __half2 h; *reinterpret_cast<unsigned*>(&h) = u; return h;
}

// ================= weight prep =================
__global__ void prep_kernel(const float* __restrict__ c2w, const float* __restrict__ d1w) {
    int i = blockIdx.x * 256 + threadIdx.x;
    if (i < 18432) {
        int oc = i / 288, r = i % 288, ic = r / 9, k = r % 9;
        g_c2wt[(ic * 9 + k) * 64 + oc] = c2w[i];
        int ic2 = i / 288, r2 = i % 288, oc2 = r2 / 9, kk = r2 % 9;
        g_d1wt[(ic2 * 9 + (8 - kk)) * 32 + oc2] = d1w[i];
    }
}

// ================= encoder + input projection (unchanged) =================
__global__ void __launch_bounds__(128) enc_kernel(
    const float* __restrict__ img, const float* __restrict__ act,
    const float* __restrict__ c1w, const float* __restrict__ c1b,
    const float* __restrict__ c2b,
    const float* __restrict__ encw, const float* __restrict__ encb,
    const float* __restrict__ wih, const float* __restrict__ bih,
    const float* __restrict__ bhh, int B)
{
    __shared__ float s_img[4][76];
    __shared__ float s_x[4][136];
    __shared__ float s_h2[4][1600];
    __shared__ float s_wt[4608];

    int tid = threadIdx.x, lane = tid & 31, w = tid >> 5;
    int gi = blockIdx.x * 4 + w;
    bool valid = gi < B;
    float* s_h1 = s_wt + w * 800;

    if (valid) {
        for (int i = lane; i < 75; i += 32) s_img[w][i] = img[gi * 75 + i];
        if (lane < 8) s_x[w][128 + lane] = act[gi * 8 + lane];
    }
    __syncwarp();

    int pidx[9];
    {
        int y = (lane < 25) ? lane / 5 : 0, x = (lane < 25) ? lane % 5 : 0;
        #pragma unroll
        for (int ky = 0; ky < 3; ky++)
            #pragma unroll
            for (int kx = 0; kx < 3; kx++) {
                int yy = y + ky - 1, xx = x + kx - 1;
                pidx[ky*3+kx] = (yy >= 0 && yy < 5 && xx >= 0 && xx < 5) ? yy*5+xx : -1;
            }
    }

    if (lane < 25) {
        float p1[27];
        #pragma unroll
        for (int ic = 0; ic < 3; ic++)
            #pragma unroll
            for (int j = 0; j < 9; j++)
                p1[ic*9+j] = (pidx[j] >= 0) ? s_img[w][ic*25 + pidx[j]] : 0.f;
        #pragma unroll 4
        for (int oc = 0; oc < 32; oc++) {
            float a = __ldg(&c1b[oc]);
            #pragma unroll
            for (int k = 0; k < 27; k++) a += p1[k] * __ldg(&c1w[oc*27+k]);
            s_h1[oc*25+lane] = fmaxf(a, 0.f);
        }
    }
    __syncwarp();

    if (lane < 25) {
        unsigned long long acc2[32];
        #pragma unroll
        for (int q = 0; q < 32; q++) acc2[q] = 0ull;
        for (int ic = 0; ic < 32; ic++) {
            const float* hp = s_h1 + ic * 25;
            unsigned long long p2[9];
            #pragma unroll
            for (int j = 0; j < 9; j++)
                p2[j] = pk2((pidx[j] >= 0) ? hp[pidx[j]] : 0.f);
            const ulonglong2* wt = reinterpret_cast<const ulonglong2*>(&g_c2wt[ic * 576]);
            #pragma unroll
            for (int k = 0; k < 9; k++) {
                #pragma unroll
                for (int q = 0; q < 16; q++) {
                    ulonglong2 wv = __ldg(&wt[k*16 + q]);
                    fma2(acc2[q*2],   p2[k], wv.x);
                    fma2(acc2[q*2+1], p2[k], wv.y);
                }
            }
        }
        #pragma unroll
        for (int q = 0; q < 32; q++) {
            float2 v = upk2(acc2[q]);
            s_h2[w][(2*q)*25   + lane] = fmaxf(v.x + __ldg(&c2b[2*q]),   0.f);
            s_h2[w][(2*q+1)*25 + lane] = fmaxf(v.y + __ldg(&c2b[2*q+1]), 0.f);
        }
    }
    __syncthreads();

    for (int ot = 0; ot < 4; ot++) {
        float acc = 0.f;
        for (int kt = 0; kt < 13; kt++) {
            int k0 = kt * 128, klen = (kt == 12) ? 64 : 128;
            __syncthreads();
            for (int idx = tid; idx < 32 * klen; idx += 128) {
                int r = idx / klen, k = idx - r * klen;
                s_wt[r*132 + k] = encw[(ot*32 + r)*1600 + k0 + k];
            }
            __syncthreads();
            const float4* wt4 = reinterpret_cast<const float4*>(&s_wt[lane*132]);
            const float4* h4  = reinterpret_cast<const float4*>(&s_h2[w][k0]);
            int n4 = klen >> 2;
            #pragma unroll 8
            for (int q = 0; q < n4; q++) {
                float4 wv = wt4[q], hv = h4[q];
                acc += wv.x*hv.x + wv.y*hv.y + wv.z*hv.z + wv.w*hv.w;
            }
        }
        s_x[w][ot*32 + lane] = acc + __ldg(&encb[ot*32 + lane]);
    }

    for (int ot = 0; ot < 16; ot++) {
        __syncthreads();
        for (int idx = tid; idx < 32 * 136; idx += 128) {
            int r = idx / 136, k = idx - r * 136;
            s_wt[r*144 + k] = wih[(ot*32 + r)*136 + k];
        }
        __syncthreads();
        float acc = 0.f;
        const float4* wt4 = reinterpret_cast<const float4*>(&s_wt[lane*144]);
        const float4* xv4 = reinterpret_cast<const float4*>(&s_x[w][0]);
        #pragma unroll 17
        for (int q = 0; q < 34; q++) {
            float4 wv = wt4[q], xv = xv4[q];
            acc += wv.x*xv.x + wv.y*xv.y + wv.z*xv.z + wv.w*xv.w;
        }
        if (valid) {
            int o = ot*32 + lane;
            g_xp[gi*512 + o] = acc + __ldg(&bih[o]) + __ldg(&bhh[o]);
        }
    }
}

// ================= LSTM: R11 structure + MUFU-only activations =================
// Thread tid: gate = tid>>7, row = tid&127, 64 half2 weights in registers.
// Per step: ONE global barrier (s_act, double-buffered) + ONE 128-thread
// named barrier per gate group (group-private s_h copy). Epilogue replicated.
__global__ void __launch_bounds__(512) lstm_kernel(
    const float* __restrict__ whh, float* __restrict__ d_out, int B, int out_size)
{
    if (blockIdx.x != 0) return;

    __shared__ __align__(16) __half s_h[4][2][128];   // per-group double-buffered h
    __shared__ float s_act[2][512];                   // double-buffered activations

    int tid = threadIdx.x;
    int gate = tid >> 7;                 // 0:i 1:f 2:g 3:o (warp-uniform)
    int row = tid & 127;

    __half2 w2[64];
    {
        const float4* rw = reinterpret_cast<const float4*>(&whh[tid * 128]);
        #pragma unroll
        for (int j = 0; j < 32; j++) {
            float4 v = __ldg(&rw[j]);
            w2[2*j]   = __floats2half2_rn(v.x, v.y);
            w2[2*j+1] = __floats2half2_rn(v.z, v.w);
        }
    }
    if (tid < 128) {
        __half z = __float2half_rn(0.f);
        #pragma unroll
        for (int g = 0; g < 4; g++) s_h[g][0][tid] = z;
    }

    float xp0 = __ldg(&g_xp[tid]);
    float xp1 = (B > 1) ? __ldg(&g_xp[512 + tid]) : 0.f;
    __syncthreads();

    float c = 0.f;   // replicated: identical in all 4 groups for this row
    for (int t = 0; t < B; t++) {
        // ---- matvec on group-private h buffer ----
        const uint4* sh4 = reinterpret_cast<const uint4*>(s_h[gate][t & 1]);
        __half2 hacc[4];
        #pragma unroll
        for (int ch = 0; ch < 4; ch++) {
            unsigned hw[16];
            uint4 q0 = sh4[ch*4+0], q1 = sh4[ch*4+1], q2 = sh4[ch*4+2], q3 = sh4[ch*4+3];
            hw[0]=q0.x; hw[1]=q0.y; hw[2]=q0.z; hw[3]=q0.w;
            hw[4]=q1.x; hw[5]=q1.y; hw[6]=q1.z; hw[7]=q1.w;
            hw[8]=q2.x; hw[9]=q2.y; hw[10]=q2.z; hw[11]=q2.w;
            hw[12]=q3.x; hw[13]=q3.y; hw[14]=q3.z; hw[15]=q3.w;
            __half2 acc = __float2half2_rn(0.f);
            #pragma unroll
            for (int j = 0; j < 16; j++)
                acc = __hfma2(w2[ch*16 + j], u2h2(hw[j]), acc);
            hacc[ch] = acc;
        }
        __half2 s01 = __hadd2(hacc[0], hacc[1]);
        __half2 s23 = __hadd2(hacc[2], hacc[3]);
        float2 fs = __half22float2(__hadd2(s01, s23));
        float pre = xp0 + fs.x + fs.y;

        xp0 = xp1;
        if (t + 2 < B) xp1 = __ldg(&g_xp[(t+2)*512 + tid]);

        float a = (gate == 2) ? ftanh(pre) : fsig(pre);   // warp-uniform branch
        s_act[t & 1][tid] = a;
        __syncthreads();                                  // global: acts ready

        // ---- replicated epilogue ----
        const float* ab = s_act[t & 1];
        float gi = ab[row];
        float gf = ab[128 + row];
        float gg = ab[256 + row];
        float go = ab[384 + row];
        c = fmaf(gf, c, gi * gg);
        float h = go * ftanh(c);
        s_h[gate][(t + 1) & 1][row] = __float2half_rn(h);
        if (gate == 0) {
            g_hs[t*128 + row] = h;
            if (t == B - 1) {
                d_out[out_size - 256 + row] = h;
                d_out[out_size - 128 + row] = c;
            }
        }
        asm volatile("bar.sync %0, 128;" :: "r"(gate + 1) : "memory");
    }
}

// ================= decoder (unchanged) =================
__global__ void __launch_bounds__(128) dec_kernel(
    const float* __restrict__ decw, const float* __restrict__ decb,
    const float* __restrict__ d1b,
    const float* __restrict__ d2w, const float* __restrict__ d2b,
    float* __restrict__ out, int B)
{
    __shared__ float s_hs[4][128];
    __shared__ float s_d[4][1600];
    __shared__ float s_wt[4224];
    __shared__ float s_w2f[864];

    int tid = threadIdx.x, lane = tid & 31, w = tid >> 5;
    int gi = blockIdx.x * 4 + w;
    bool valid = gi < B;

    for (int i = tid; i < 864; i += 128) {
        int ic = i / 27, rem = i % 27, oc = rem / 9, k = rem % 9;
        s_w2f[i] = d2w[(ic*3 + oc)*9 + (8 - k)];
    }
    if (valid)
        for (int i = lane; i < 128; i += 32) s_hs[w][i] = g_hs[gi*128 + i];

    for (int ot = 0; ot < 50; ot++) {
        __syncthreads();
        for (int idx = tid; idx < 4096; idx += 128) {
            int r = idx >> 7, k = idx & 127;
            s_wt[r*132 + k] = decw[(ot*32 + r)*128 + k];
        }
        __syncthreads();
        float acc = 0.f;
        const float4* wt4 = reinterpret_cast<const float4*>(&s_wt[lane*132]);
        const float4* h4  = reinterpret_cast<const float4*>(&s_hs[w][0]);
        #pragma unroll 8
        for (int q = 0; q < 32; q++) {
            float4 wv = wt4[q], hv = h4[q];
            acc += wv.x*hv.x + wv.y*hv.y + wv.z*hv.z + wv.w*hv.w;
        }
        s_d[w][ot*32 + lane] = acc + __ldg(&decb[ot*32 + lane]);
    }
    __syncthreads();

    float* s_h1 = s_wt + w * 800;
    int pidx[9];
    {
        int y = (lane < 25) ? lane / 5 : 0, x = (lane < 25) ? lane % 5 : 0;
        #pragma unroll
        for (int ky = 0; ky < 3; ky++)
            #pragma unroll
            for (int kx = 0; kx < 3; kx++) {
                int yy = y + ky - 1, xx = x + kx - 1;
                pidx[ky*3+kx] = (yy >= 0 && yy < 5 && xx >= 0 && xx < 5) ? yy*5+xx : -1;
            }
    }

    if (lane < 25) {
        unsigned long long acc2[16];
        #pragma unroll
        for (int q = 0; q < 16; q++) acc2[q] = 0ull;
        for (int ic = 0; ic < 64; ic++) {
            const float* dp = &s_d[w][ic * 25];
            unsigned long long p2[9];
            #pragma unroll
            for (int j = 0; j < 9; j++)
                p2[j] = pk2((pidx[j] >= 0) ? dp[pidx[j]] : 0.f);
            const ulonglong2* wt = reinterpret_cast<const ulonglong2*>(&g_d1wt[ic * 288]);
            #pragma unroll
            for (int k = 0; k < 9; k++) {
                #pragma unroll
                for (int q = 0; q < 8; q++) {
                    ulonglong2 wv = __ldg(&wt[k*8 + q]);
                    fma2(acc2[q*2],   p2[k], wv.x);
                    fma2(acc2[q*2+1], p2[k], wv.y);
                }
            }
        }
        #pragma unroll
        for (int q = 0; q < 16; q++) {
            float2 v = upk2(acc2[q]);
            s_h1[(2*q)*25   + lane] = fmaxf(v.x + __ldg(&d1b[2*q]),   0.f);
            s_h1[(2*q+1)*25 + lane] = fmaxf(v.y + __ldg(&d1b[2*q+1]), 0.f);
        }
    }
    __syncwarp();

    if (valid && lane < 25) {
        float acc[3] = {__ldg(&d2b[0]), __ldg(&d2b[1]), __ldg(&d2b[2])};
        for (int ic = 0; ic < 32; ic++) {
            float p[9];
            #pragma unroll
            for (int j = 0; j < 9; j++)
                p[j] = (pidx[j] >= 0) ? s_h1[ic*25 + pidx[j]] : 0.f;
            #pragma unroll
            for (int oc = 0; oc < 3; oc++) {
                float a = acc[oc];
                #pragma unroll
                for (int k = 0; k < 9; k++) a += p[k] * s_w2f[ic*27 + oc*9 + k];
                acc[oc] = a;
            }
        }
        #pragma unroll
        for (int oc = 0; oc < 3; oc++)
            out[gi*75 + oc*25 + lane] = fsig(acc[oc]);
    }
}

extern "C" void kernel_launch(void* const* d_in, const int* in_sizes, int n_in,
                              void* d_out, int out_size)
{
    const float* img   = (const float*)d_in[0];
    const float* act   = (const float*)d_in[1];
    const float* c1w   = (const float*)d_in[2];
    const float* c1b   = (const float*)d_in[3];
    const float* c2w   = (const float*)d_in[4];
    const float* c2b   = (const float*)d_in[5];
    const float* encw  = (const float*)d_in[6];
    const float* encb  = (const float*)d_in[7];
    const float* wih   = (const float*)d_in[8];
    const float* whh   = (const float*)d_in[9];
    const float* bih   = (const float*)d_in[10];
    const float* bhh   = (const float*)d_in[11];
    const float* decw  = (const float*)d_in[12];
    const float* decb  = (const float*)d_in[13];
    const float* d1w   = (const float*)d_in[14];
    const float* d1b   = (const float*)d_in[15];
    const float* d2w   = (const float*)d_in[16];
    const float* d2b   = (const float*)d_in[17];
    float* out = (float*)d_out;

    int B = in_sizes[0] / 75;
    int blocks = (B + 3) / 4;

    prep_kernel<<<72, 256>>>(c2w, d1w);
    enc_kernel<<<blocks, 128>>>(img, act, c1w, c1b, c2b, encw, encb, wih, bih, bhh, B);
    lstm_kernel<<<148, 512>>>(whh, out, B, out_size);
    dec_kernel<<<blocks, 128>>>(decw, decb, d1b, d2w, d2b, out, B);
}

// round 15
// speedup vs baseline: 1.9292x; 1.0979x over previous
#include <cuda_runtime.h>
#include <cuda_fp16.h>
#include <cstdint>

#define BMAX 16384
__device__ float g_xp[BMAX * 512];
__device__ float g_hs[BMAX * 128];
__device__ float g_c2wt[32 * 9 * 64];   // conv2 weights [ic][k][oc]
__device__ float g_d1wt[64 * 9 * 32];   // deconv1 conv-equiv weights [ic][k][oc]

// enc/dec activations (unchanged from R14)
__device__ __forceinline__ float fsig(float x) { return __fdividef(1.0f, 1.0f + __expf(-x)); }
// LSTM activations: single-MUFU tanh.approx
__device__ __forceinline__ float ltanh(float x) {
    float y; asm("tanh.approx.f32 %0, %1;" : "=f"(y) : "f"(x)); return y;
}
__device__ __forceinline__ float lsig(float x) {
    return fmaf(0.5f, ltanh(0.5f * x), 0.5f);
}
__device__ __forceinline__ void fma2(unsigned long long& acc, unsigned long long a, unsigned long long b) {
    asm("fma.rn.f32x2 %0, %1, %2, %0;" : "+l"(acc) : "l"(a), "l"(b));
}
__device__ __forceinline__ unsigned long long pk2(float x) {
    unsigned long long r; asm("mov.b64 %0, {%1,%2};" : "=l"(r) : "f"(x), "f"(x)); return r;
}
__device__ __forceinline__ float2 upk2(unsigned long long v) {
    float2 r; asm("mov.b64 {%0,%1}, %2;" : "=f"(r.x), "=f"(r.y) : "l"(v)); return r;
}
__device__ __forceinline__ __half2 u2h2(unsigned u) {
    __half2 h; *reinterpret_cast<unsigned*>(&h) = u; return h;
}

// ================= weight prep =================
__global__ void prep_kernel(const float* __restrict__ c2w, const float* __restrict__ d1w) {
    int i = blockIdx.x * 256 + threadIdx.x;
    if (i < 18432) {
        int oc = i / 288, r = i % 288, ic = r / 9, k = r % 9;
        g_c2wt[(ic * 9 + k) * 64 + oc] = c2w[i];
        int ic2 = i / 288, r2 = i % 288, oc2 = r2 / 9, kk = r2 % 9;
        g_d1wt[(ic2 * 9 + (8 - kk)) * 32 + oc2] = d1w[i];
    }
}

// ================= encoder + input projection (unchanged) =================
__global__ void __launch_bounds__(128) enc_kernel(
    const float* __restrict__ img, const float* __restrict__ act,
    const float* __restrict__ c1w, const float* __restrict__ c1b,
    const float* __restrict__ c2b,
    const float* __restrict__ encw, const float* __restrict__ encb,
    const float* __restrict__ wih, const float* __restrict__ bih,
    const float* __restrict__ bhh, int B)
{
    __shared__ float s_img[4][76];
    __shared__ float s_x[4][136];
    __shared__ float s_h2[4][1600];
    __shared__ float s_wt[4608];

    int tid = threadIdx.x, lane = tid & 31, w = tid >> 5;
    int gi = blockIdx.x * 4 + w;
    bool valid = gi < B;
    float* s_h1 = s_wt + w * 800;

    if (valid) {
        for (int i = lane; i < 75; i += 32) s_img[w][i] = img[gi * 75 + i];
        if (lane < 8) s_x[w][128 + lane] = act[gi * 8 + lane];
    }
    __syncwarp();

    int pidx[9];
    {
        int y = (lane < 25) ? lane / 5 : 0, x = (lane < 25) ? lane % 5 : 0;
        #pragma unroll
        for (int ky = 0; ky < 3; ky++)
            #pragma unroll
            for (int kx = 0; kx < 3; kx++) {
                int yy = y + ky - 1, xx = x + kx - 1;
                pidx[ky*3+kx] = (yy >= 0 && yy < 5 && xx >= 0 && xx < 5) ? yy*5+xx : -1;
            }
    }

    if (lane < 25) {
        float p1[27];
        #pragma unroll
        for (int ic = 0; ic < 3; ic++)
            #pragma unroll
            for (int j = 0; j < 9; j++)
                p1[ic*9+j] = (pidx[j] >= 0) ? s_img[w][ic*25 + pidx[j]] : 0.f;
        #pragma unroll 4
        for (int oc = 0; oc < 32; oc++) {
            float a = __ldg(&c1b[oc]);
            #pragma unroll
            for (int k = 0; k < 27; k++) a += p1[k] * __ldg(&c1w[oc*27+k]);
            s_h1[oc*25+lane] = fmaxf(a, 0.f);
        }
    }
    __syncwarp();

    if (lane < 25) {
        unsigned long long acc2[32];
        #pragma unroll
        for (int q = 0; q < 32; q++) acc2[q] = 0ull;
        for (int ic = 0; ic < 32; ic++) {
            const float* hp = s_h1 + ic * 25;
            unsigned long long p2[9];
            #pragma unroll
            for (int j = 0; j < 9; j++)
                p2[j] = pk2((pidx[j] >= 0) ? hp[pidx[j]] : 0.f);
            const ulonglong2* wt = reinterpret_cast<const ulonglong2*>(&g_c2wt[ic * 576]);
            #pragma unroll
            for (int k = 0; k < 9; k++) {
                #pragma unroll
                for (int q = 0; q < 16; q++) {
                    ulonglong2 wv = __ldg(&wt[k*16 + q]);
                    fma2(acc2[q*2],   p2[k], wv.x);
                    fma2(acc2[q*2+1], p2[k], wv.y);
                }
            }
        }
        #pragma unroll
        for (int q = 0; q < 32; q++) {
            float2 v = upk2(acc2[q]);
            s_h2[w][(2*q)*25   + lane] = fmaxf(v.x + __ldg(&c2b[2*q]),   0.f);
            s_h2[w][(2*q+1)*25 + lane] = fmaxf(v.y + __ldg(&c2b[2*q+1]), 0.f);
        }
    }
    __syncthreads();

    for (int ot = 0; ot < 4; ot++) {
        float acc = 0.f;
        for (int kt = 0; kt < 13; kt++) {
            int k0 = kt * 128, klen = (kt == 12) ? 64 : 128;
            __syncthreads();
            for (int idx = tid; idx < 32 * klen; idx += 128) {
                int r = idx / klen, k = idx - r * klen;
                s_wt[r*132 + k] = encw[(ot*32 + r)*1600 + k0 + k];
            }
            __syncthreads();
            const float4* wt4 = reinterpret_cast<const float4*>(&s_wt[lane*132]);
            const float4* h4  = reinterpret_cast<const float4*>(&s_h2[w][k0]);
            int n4 = klen >> 2;
            #pragma unroll 8
            for (int q = 0; q < n4; q++) {
                float4 wv = wt4[q], hv = h4[q];
                acc += wv.x*hv.x + wv.y*hv.y + wv.z*hv.z + wv.w*hv.w;
            }
        }
        s_x[w][ot*32 + lane] = acc + __ldg(&encb[ot*32 + lane]);
    }

    for (int ot = 0; ot < 16; ot++) {
        __syncthreads();
        for (int idx = tid; idx < 32 * 136; idx += 128) {
            int r = idx / 136, k = idx - r * 136;
            s_wt[r*144 + k] = wih[(ot*32 + r)*136 + k];
        }
        __syncthreads();
        float acc = 0.f;
        const float4* wt4 = reinterpret_cast<const float4*>(&s_wt[lane*144]);
        const float4* xv4 = reinterpret_cast<const float4*>(&s_x[w][0]);
        #pragma unroll 17
        for (int q = 0; q < 34; q++) {
            float4 wv = wt4[q], xv = xv4[q];
            acc += wv.x*xv.x + wv.y*xv.y + wv.z*xv.z + wv.w*xv.w;
        }
        if (valid) {
            int o = ot*32 + lane;
            g_xp[gi*512 + o] = acc + __ldg(&bih[o]) + __ldg(&bhh[o]);
        }
    }
}

// ================= LSTM: R14 structure + tanh.approx activations =================
// Thread tid: gate = tid>>7, row = tid&127, 64 half2 weights in registers.
// Per step: ONE global barrier (s_act, double-buffered) + ONE 128-thread
// named barrier per gate group (group-private s_h copy). Epilogue replicated.
// Activations: 1 MUFU each (tanh.approx; sigmoid = 0.5*tanh(x/2)+0.5).
__global__ void __launch_bounds__(512) lstm_kernel(
    const float* __restrict__ whh, float* __restrict__ d_out, int B, int out_size)
{
    if (blockIdx.x != 0) return;

    __shared__ __align__(16) __half s_h[4][2][128];   // per-group double-buffered h
    __shared__ float s_act[2][512];                   // double-buffered activations

    int tid = threadIdx.x;
    int gate = tid >> 7;                 // 0:i 1:f 2:g 3:o (warp-uniform)
    int row = tid & 127;

    __half2 w2[64];
    {
        const float4* rw = reinterpret_cast<const float4*>(&whh[tid * 128]);
        #pragma unroll
        for (int j = 0; j < 32; j++) {
            float4 v = __ldg(&rw[j]);
            w2[2*j]   = __floats2half2_rn(v.x, v.y);
            w2[2*j+1] = __floats2half2_rn(v.z, v.w);
        }
    }
    if (tid < 128) {
        __half z = __float2half_rn(0.f);
        #pragma unroll
        for (int g = 0; g < 4; g++) s_h[g][0][tid] = z;
    }

    float xp0 = __ldg(&g_xp[tid]);
    float xp1 = (B > 1) ? __ldg(&g_xp[512 + tid]) : 0.f;
    __syncthreads();

    float c = 0.f;   // replicated: identical in all 4 groups for this row
    for (int t = 0; t < B; t++) {
        // ---- matvec on group-private h buffer ----
        const uint4* sh4 = reinterpret_cast<const uint4*>(s_h[gate][t & 1]);
        __half2 hacc[4];
        #pragma unroll
        for (int ch = 0; ch < 4; ch++) {
            unsigned hw[16];
            uint4 q0 = sh4[ch*4+0], q1 = sh4[ch*4+1], q2 = sh4[ch*4+2], q3 = sh4[ch*4+3];
            hw[0]=q0.x; hw[1]=q0.y; hw[2]=q0.z; hw[3]=q0.w;
            hw[4]=q1.x; hw[5]=q1.y; hw[6]=q1.z; hw[7]=q1.w;
            hw[8]=q2.x; hw[9]=q2.y; hw[10]=q2.z; hw[11]=q2.w;
            hw[12]=q3.x; hw[13]=q3.y; hw[14]=q3.z; hw[15]=q3.w;
            __half2 acc = __float2half2_rn(0.f);
            #pragma unroll
            for (int j = 0; j < 16; j++)
                acc = __hfma2(w2[ch*16 + j], u2h2(hw[j]), acc);
            hacc[ch] = acc;
        }
        __half2 s01 = __hadd2(hacc[0], hacc[1]);
        __half2 s23 = __hadd2(hacc[2], hacc[3]);
        float2 fs = __half22float2(__hadd2(s01, s23));
        float pre = xp0 + fs.x + fs.y;

        xp0 = xp1;
        if (t + 2 < B) xp1 = __ldg(&g_xp[(t+2)*512 + tid]);

        float a = (gate == 2) ? ltanh(pre) : lsig(pre);   // 1 MUFU either way
        s_act[t & 1][tid] = a;
        __syncthreads();                                  // global: acts ready

        // ---- replicated epilogue ----
        const float* ab = s_act[t & 1];
        float gi = ab[row];
        float gf = ab[128 + row];
        float gg = ab[256 + row];
        float go = ab[384 + row];
        c = fmaf(gf, c, gi * gg);
        float h = go * ltanh(c);
        s_h[gate][(t + 1) & 1][row] = __float2half_rn(h);
        if (gate == 0) {
            g_hs[t*128 + row] = h;
            if (t == B - 1) {
                d_out[out_size - 256 + row] = h;
                d_out[out_size - 128 + row] = c;
            }
        }
        asm volatile("bar.sync %0, 128;" :: "r"(gate + 1) : "memory");
    }
}

// ================= decoder (unchanged) =================
__global__ void __launch_bounds__(128) dec_kernel(
    const float* __restrict__ decw, const float* __restrict__ decb,
    const float* __restrict__ d1b,
    const float* __restrict__ d2w, const float* __restrict__ d2b,
    float* __restrict__ out, int B)
{
    __shared__ float s_hs[4][128];
    __shared__ float s_d[4][1600];
    __shared__ float s_wt[4224];
    __shared__ float s_w2f[864];

    int tid = threadIdx.x, lane = tid & 31, w = tid >> 5;
    int gi = blockIdx.x * 4 + w;
    bool valid = gi < B;

    for (int i = tid; i < 864; i += 128) {
        int ic = i / 27, rem = i % 27, oc = rem / 9, k = rem % 9;
        s_w2f[i] = d2w[(ic*3 + oc)*9 + (8 - k)];
    }
    if (valid)
        for (int i = lane; i < 128; i += 32) s_hs[w][i] = g_hs[gi*128 + i];

    for (int ot = 0; ot < 50; ot++) {
        __syncthreads();
        for (int idx = tid; idx < 4096; idx += 128) {
            int r = idx >> 7, k = idx & 127;
            s_wt[r*132 + k] = decw[(ot*32 + r)*128 + k];
        }
        __syncthreads();
        float acc = 0.f;
        const float4* wt4 = reinterpret_cast<const float4*>(&s_wt[lane*132]);
        const float4* h4  = reinterpret_cast<const float4*>(&s_hs[w][0]);
        #pragma unroll 8
        for (int q = 0; q < 32; q++) {
            float4 wv = wt4[q], hv = h4[q];
            acc += wv.x*hv.x + wv.y*hv.y + wv.z*hv.z + wv.w*hv.w;
        }
        s_d[w][ot*32 + lane] = acc + __ldg(&decb[ot*32 + lane]);
    }
    __syncthreads();

    float* s_h1 = s_wt + w * 800;
    int pidx[9];
    {
        int y = (lane < 25) ? lane / 5 : 0, x = (lane < 25) ? lane % 5 : 0;
        #pragma unroll
        for (int ky = 0; ky < 3; ky++)
            #pragma unroll
            for (int kx = 0; kx < 3; kx++) {
                int yy = y + ky - 1, xx = x + kx - 1;
                pidx[ky*3+kx] = (yy >= 0 && yy < 5 && xx >= 0 && xx < 5) ? yy*5+xx : -1;
            }
    }

    if (lane < 25) {
        unsigned long long acc2[16];
        #pragma unroll
        for (int q = 0; q < 16; q++) acc2[q] = 0ull;
        for (int ic = 0; ic < 64; ic++) {
            const float* dp = &s_d[w][ic * 25];
            unsigned long long p2[9];
            #pragma unroll
            for (int j = 0; j < 9; j++)
                p2[j] = pk2((pidx[j] >= 0) ? dp[pidx[j]] : 0.f);
            const ulonglong2* wt = reinterpret_cast<const ulonglong2*>(&g_d1wt[ic * 288]);
            #pragma unroll
            for (int k = 0; k < 9; k++) {
                #pragma unroll
                for (int q = 0; q < 8; q++) {
                    ulonglong2 wv = __ldg(&wt[k*8 + q]);
                    fma2(acc2[q*2],   p2[k], wv.x);
                    fma2(acc2[q*2+1], p2[k], wv.y);
                }
            }
        }
        #pragma unroll
        for (int q = 0; q < 16; q++) {
            float2 v = upk2(acc2[q]);
            s_h1[(2*q)*25   + lane] = fmaxf(v.x + __ldg(&d1b[2*q]),   0.f);
            s_h1[(2*q+1)*25 + lane] = fmaxf(v.y + __ldg(&d1b[2*q+1]), 0.f);
        }
    }
    __syncwarp();

    if (valid && lane < 25) {
        float acc[3] = {__ldg(&d2b[0]), __ldg(&d2b[1]), __ldg(&d2b[2])};
        for (int ic = 0; ic < 32; ic++) {
            float p[9];
            #pragma unroll
            for (int j = 0; j < 9; j++)
                p[j] = (pidx[j] >= 0) ? s_h1[ic*25 + pidx[j]] : 0.f;
            #pragma unroll
            for (int oc = 0; oc < 3; oc++) {
                float a = acc[oc];
                #pragma unroll
                for (int k = 0; k < 9; k++) a += p[k] * s_w2f[ic*27 + oc*9 + k];
                acc[oc] = a;
            }
        }
        #pragma unroll
        for (int oc = 0; oc < 3; oc++)
            out[gi*75 + oc*25 + lane] = fsig(acc[oc]);
    }
}

extern "C" void kernel_launch(void* const* d_in, const int* in_sizes, int n_in,
                              void* d_out, int out_size)
{
    const float* img   = (const float*)d_in[0];
    const float* act   = (const float*)d_in[1];
    const float* c1w   = (const float*)d_in[2];
    const float* c1b   = (const float*)d_in[3];
    const float* c2w   = (const float*)d_in[4];
    const float* c2b   = (const float*)d_in[5];
    const float* encw  = (const float*)d_in[6];
    const float* encb  = (const float*)d_in[7];
    const float* wih   = (const float*)d_in[8];
    const float* whh   = (const float*)d_in[9];
    const float* bih   = (const float*)d_in[10];
    const float* bhh   = (const float*)d_in[11];
    const float* decw  = (const float*)d_in[12];
    const float* decb  = (const float*)d_in[13];
    const float* d1w   = (const float*)d_in[14];
    const float* d1b   = (const float*)d_in[15];
    const float* d2w   = (const float*)d_in[16];
    const float* d2b   = (const float*)d_in[17];
    float* out = (float*)d_out;

    int B = in_sizes[0] / 75;
    int blocks = (B + 3) / 4;

    prep_kernel<<<72, 256>>>(c2w, d1w);
    enc_kernel<<<blocks, 128>>>(img, act, c1w, c1b, c2b, encw, encb, wih, bih, bhh, B);
    lstm_kernel<<<148, 512>>>(whh, out, B, out_size);
    dec_kernel<<<blocks, 128>>>(decw, decb, d1b, d2w, d2b, out, B);
}